// round 16
// baseline (speedup 1.0000x reference)
#include <cuda_runtime.h>
#include <cuda.h>
#include <cuda_bf16.h>
#include <mma.h>
#include <cstdint>
#include <cstring>

#define SEQ   16384
#define DIM   1280
#define NH    16
#define HD    80
#define WIN   64
#define NWIN  (SEQ / WIN)
#define HDP   84
#define PSP   68   // P row stride (16B-aligned)
#define VTS   68   // vT row stride (16B-aligned)

// tcgen05 cg2 GEMM tiling: persistent pairs, 256x256 pair tile
#define TM    128
#define TN    256
#define TKE   64
#define KSTG  (DIM / TKE)  // 20
#define NBUF  3
#define NPAIR 74
#define MT    64           // SEQ/256

// smem layout (gemm)
#define SM_TMEM   0
#define SM_FULL   8
#define SM_DONE   32
#define SM_TILED  56
#define SM_BANKF  72
#define SM_BUF    1024
#define AB_QTR    16384
#define STAGE_BYTES (4 * AB_QTR)
#define SMEM_GEMM (SM_BUF + NBUF * STAGE_BYTES)
#define STAGE_TX  (2 * STAGE_BYTES)

// attention smem: qs[64][84] + ks[64][84] + vT[80][68]
#define SMEM_ATTN ((2 * WIN * HDP + HD * VTS) * (int)sizeof(float))  // 64,768 B

#if defined(__CUDA_ARCH__) && (defined(__CUDA_ARCH_FEAT_SM103_ALL) || defined(__CUDA_ARCH_FEAT_SM100_ALL))
#define TC_PATH 1
#else
#define TC_PATH 0
#endif

// ---------------------------------------------------------------------------
__device__ float g_q[SEQ * DIM];
__device__ float g_k[SEQ * DIM];
__device__ float g_v[SEQ * DIM];
__device__ __nv_bfloat16 g_ahi[SEQ * DIM];
__device__ __nv_bfloat16 g_alo[SEQ * DIM];
__device__ __nv_bfloat16 g_whi[3 * DIM * DIM];
__device__ __nv_bfloat16 g_wlo[3 * DIM * DIM];

// packed fp32x2 FMA accumulate: d += a*b (elementwise), d/a/b are 2xf32
__device__ __forceinline__ void fma2(unsigned long long& d,
                                     unsigned long long a, unsigned long long b) {
#if TC_PATH
    asm("fma.rn.f32x2 %0, %1, %2, %0;" : "+l"(d) : "l"(a), "l"(b));
#else
    float2 df, af, bf;
    memcpy(&df, &d, 8); memcpy(&af, &a, 8); memcpy(&bf, &b, 8);
    df.x = fmaf(af.x, bf.x, df.x);
    df.y = fmaf(af.y, bf.y, df.y);
    memcpy(&d, &df, 8);
#endif
}
__device__ __forceinline__ float hadd2(unsigned long long v) {
    float2 f;
    memcpy(&f, &v, 8);
    return f.x + f.y;
}

#if TC_PATH
__device__ __forceinline__ uint32_t smem_u32(const void* p) {
    uint32_t a;
    asm("{ .reg .u64 t; cvta.to.shared.u64 t, %1; cvt.u32.u64 %0, t; }"
        : "=r"(a) : "l"(p));
    return a;
}
__device__ __forceinline__ uint32_t ctarank() {
    uint32_t r;
    asm("mov.u32 %0, %%cluster_ctarank;" : "=r"(r));
    return r;
}
#define MBAR_INIT(addr, cnt) \
    asm volatile("mbarrier.init.shared.b64 [%0], %1;" :: "r"(addr), "r"(cnt) : "memory")
#define MBAR_EXPECT_TX(addr, tx) \
    asm volatile("mbarrier.arrive.expect_tx.shared.b64 _, [%0], %1;" :: "r"(addr), "r"(tx) : "memory")
#define MBAR_ARRIVE_LEADER(addr) \
    asm volatile("{ .reg .b32 la; and.b32 la, %0, 0xFEFFFFFF; " \
                 "mbarrier.arrive.shared::cluster.b64 _, [la]; }" :: "r"(addr) : "memory")

__device__ __forceinline__ void mbar_wait(uint32_t mbar, uint32_t phase) {
    asm volatile(
        "{\n\t.reg .pred P;\n\t"
        "WL_%=:\n\t"
        "mbarrier.try_wait.parity.acquire.cta.shared::cta.b64 P, [%0], %1, 0x989680;\n\t"
        "@P bra WD_%=;\n\t"
        "bra WL_%=;\n\t"
        "WD_%=:\n\t}"
        :: "r"(mbar), "r"(phase) : "memory");
}
#define CLUSTER_SYNC() do { \
    asm volatile("barrier.cluster.arrive.aligned;" ::: "memory"); \
    asm volatile("barrier.cluster.wait.aligned;" ::: "memory"); \
} while (0)

__device__ __forceinline__ void tma2d_cg2(uint32_t saddr, const void* tmap, int x, int y,
                                          uint32_t mbar) {
    asm volatile(
        "{\n\t.reg .b32 lb;\n\tand.b32 lb, %4, 0xFEFFFFFF;\n\t"
        "cp.async.bulk.tensor.2d.cta_group::2.shared::cluster.global.tile"
        ".mbarrier::complete_tx::bytes [%0], [%1, {%2, %3}], [lb];\n\t}"
        :: "r"(saddr), "l"(tmap), "r"(x), "r"(y), "r"(mbar) : "memory");
}
__device__ __forceinline__ uint64_t mk_desc(uint32_t addr) {
    return ((uint64_t)2 << 61) | ((uint64_t)1 << 46) | ((uint64_t)64 << 32) |
           ((uint64_t)1 << 16) | (uint64_t)((addr >> 4) & 0x3FFF);
}
__device__ __forceinline__ void mma_bf16_ss_cg2(uint32_t d, uint64_t ad, uint64_t bd,
                                                uint32_t idesc, uint32_t en) {
    asm volatile(
        "{\n\t.reg .pred p;\n\tsetp.ne.u32 p, %5, 0;\n\t"
        "tcgen05.mma.cta_group::2.kind::f16 [%0], %1, %2, %3, "
        "{%4, %4, %4, %4, %4, %4, %4, %4}, p;\n\t}"
        :: "r"(d), "l"(ad), "l"(bd), "r"(idesc), "r"(0u), "r"(en) : "memory");
}
#define TC_COMMIT_MC2(mbar, mask) \
    asm volatile("tcgen05.commit.cta_group::2.mbarrier::arrive::one.shared::cluster" \
                 ".multicast::cluster.b64 [%0], %1;" :: "r"(mbar), "h"((uint16_t)(mask)) : "memory")
#define TC_ALLOC2(slot, n) \
    asm volatile("tcgen05.alloc.cta_group::2.sync.aligned.shared::cta.b32 [%0], %1;" \
                 :: "r"(slot), "r"(n) : "memory")
#define TC_RELINQ2() \
    asm volatile("tcgen05.relinquish_alloc_permit.cta_group::2.sync.aligned;")
#define TC_DEALLOC2(t, n) \
    asm volatile("tcgen05.dealloc.cta_group::2.sync.aligned.b32 %0, %1;" :: "r"(t), "r"(n))
#define TC_FENCE_AFTER()  asm volatile("tcgen05.fence::after_thread_sync;" ::: "memory")
#define TC_FENCE_BEFORE() asm volatile("tcgen05.fence::before_thread_sync;" ::: "memory")
#define TC_WAIT_LD() asm volatile("tcgen05.wait::ld.sync.aligned;" ::: "memory")

#define LDTM_X32(r, addr) \
    asm volatile("tcgen05.ld.sync.aligned.32x32b.x32.b32 " \
        "{%0,%1,%2,%3,%4,%5,%6,%7,%8,%9,%10,%11,%12,%13,%14,%15," \
        "%16,%17,%18,%19,%20,%21,%22,%23,%24,%25,%26,%27,%28,%29,%30,%31}, [%32];" \
        : "=r"((r)[0]),"=r"((r)[1]),"=r"((r)[2]),"=r"((r)[3]), \
          "=r"((r)[4]),"=r"((r)[5]),"=r"((r)[6]),"=r"((r)[7]), \
          "=r"((r)[8]),"=r"((r)[9]),"=r"((r)[10]),"=r"((r)[11]), \
          "=r"((r)[12]),"=r"((r)[13]),"=r"((r)[14]),"=r"((r)[15]), \
          "=r"((r)[16]),"=r"((r)[17]),"=r"((r)[18]),"=r"((r)[19]), \
          "=r"((r)[20]),"=r"((r)[21]),"=r"((r)[22]),"=r"((r)[23]), \
          "=r"((r)[24]),"=r"((r)[25]),"=r"((r)[26]),"=r"((r)[27]), \
          "=r"((r)[28]),"=r"((r)[29]),"=r"((r)[30]),"=r"((r)[31]) \
        : "r"(addr))

#define IDESC2 ((1u << 4) | (1u << 7) | (1u << 10) | ((TN / 8) << 17) | (16u << 24))
#endif  // TC_PATH

// ---------------------------------------------------------------------------
__global__ void split_kernel(const float* __restrict__ src,
                             __nv_bfloat16* __restrict__ hi,
                             __nv_bfloat16* __restrict__ lo, int n4)
{
    int i = blockIdx.x * blockDim.x + threadIdx.x;
    if (i >= n4) return;
    float4 v = ((const float4*)src)[i];
    __nv_bfloat16 h0 = __float2bfloat16(v.x);
    __nv_bfloat16 h1 = __float2bfloat16(v.y);
    __nv_bfloat16 h2 = __float2bfloat16(v.z);
    __nv_bfloat16 h3 = __float2bfloat16(v.w);
    __nv_bfloat16 l0 = __float2bfloat16(v.x - __bfloat162float(h0));
    __nv_bfloat16 l1 = __float2bfloat16(v.y - __bfloat162float(h1));
    __nv_bfloat16 l2 = __float2bfloat16(v.z - __bfloat162float(h2));
    __nv_bfloat16 l3 = __float2bfloat16(v.w - __bfloat162float(h3));
    __nv_bfloat162* hp = (__nv_bfloat162*)hi;
    __nv_bfloat162* lp = (__nv_bfloat162*)lo;
    hp[2 * i]     = __nv_bfloat162(h0, h1);
    hp[2 * i + 1] = __nv_bfloat162(h2, h3);
    lp[2 * i]     = __nv_bfloat162(l0, l1);
    lp[2 * i + 1] = __nv_bfloat162(l2, l3);
}

// Three weight matrices in one launch
__global__ void split3_kernel(const float* __restrict__ s0,
                              const float* __restrict__ s1,
                              const float* __restrict__ s2,
                              __nv_bfloat16* __restrict__ hi,
                              __nv_bfloat16* __restrict__ lo, int n4)
{
    int gi = blockIdx.x * blockDim.x + threadIdx.x;
    int m = gi / n4;
    int i = gi - m * n4;
    if (m >= 3) return;
    const float* src = (m == 0) ? s0 : (m == 1) ? s1 : s2;
    float4 v = ((const float4*)src)[i];
    __nv_bfloat16 h0 = __float2bfloat16(v.x);
    __nv_bfloat16 h1 = __float2bfloat16(v.y);
    __nv_bfloat16 h2 = __float2bfloat16(v.z);
    __nv_bfloat16 h3 = __float2bfloat16(v.w);
    __nv_bfloat16 l0 = __float2bfloat16(v.x - __bfloat162float(h0));
    __nv_bfloat16 l1 = __float2bfloat16(v.y - __bfloat162float(h1));
    __nv_bfloat16 l2 = __float2bfloat16(v.z - __bfloat162float(h2));
    __nv_bfloat16 l3 = __float2bfloat16(v.w - __bfloat162float(h3));
    __nv_bfloat162* hp = (__nv_bfloat162*)(hi + (size_t)m * DIM * DIM);
    __nv_bfloat162* lp = (__nv_bfloat162*)(lo + (size_t)m * DIM * DIM);
    hp[2 * i]     = __nv_bfloat162(h0, h1);
    hp[2 * i + 1] = __nv_bfloat162(h2, h3);
    lp[2 * i]     = __nv_bfloat162(l0, l1);
    lp[2 * i + 1] = __nv_bfloat162(l2, l3);
}

// ---------------------------------------------------------------------------
// Persistent cg2 bf16x3 GEMM; bias added in epilogue. (Unchanged.)
// ---------------------------------------------------------------------------
__global__ __launch_bounds__(256, 1) __cluster_dims__(2, 1, 1)
void gemm_tc(const __grid_constant__ CUtensorMap tmAh,
             const __grid_constant__ CUtensorMap tmAl,
             const __grid_constant__ CUtensorMap tmBh,
             const __grid_constant__ CUtensorMap tmBl,
             const __nv_bfloat16* __restrict__ Ah,
             const __nv_bfloat16* __restrict__ Al,
             const __nv_bfloat16* __restrict__ Bh,
             const __nv_bfloat16* __restrict__ Bl,
             float* cq, float* ck, float* cv,
             const float* __restrict__ b0, const float* __restrict__ b1,
             const float* __restrict__ b2, int fused, int ntiles)
{
    extern __shared__ char smc[];
    const int tid = threadIdx.x;
    const int wid = tid >> 5;

#if TC_PATH
    const int lane = tid & 31;
    const uint32_t sbase = smem_u32(smc);
    const uint32_t rank = ctarank();
    const int p = blockIdx.x >> 1;
    const int myN = (ntiles - 1 - p) / NPAIR + 1;
    const int total = myN * KSTG;

    if (tid == 0) {
#pragma unroll
        for (int s = 0; s < NBUF; s++) {
            MBAR_INIT(sbase + SM_FULL + 8 * s, 1);
            MBAR_INIT(sbase + SM_DONE + 8 * s, 1);
        }
        MBAR_INIT(sbase + SM_TILED, 1);
        MBAR_INIT(sbase + SM_TILED + 8, 1);
        MBAR_INIT(sbase + SM_BANKF, 2);
        MBAR_INIT(sbase + SM_BANKF + 8, 2);
    }
    if (wid == 0) {
        TC_ALLOC2(sbase + SM_TMEM, 512);
        TC_RELINQ2();
    }
    __syncthreads();
    CLUSTER_SYNC();

    uint32_t tmem;
    asm volatile("ld.shared.b32 %0, [%1];" : "=r"(tmem) : "r"(sbase + SM_TMEM));

    if (tid == 224) {   // TMA producer, both CTAs
        int pd[NBUF] = {0, 0, 0};
        for (int u = 0; u < total; u++) {
            const int b = u % NBUF;
            if (u >= NBUF) {
                mbar_wait(sbase + SM_DONE + 8 * b, pd[b]);
                pd[b] ^= 1;
            }
            const int ti = u / KSTG, k = u - ti * KSTG;
            const int t = p + ti * NPAIR;
            const int pm = t & (MT - 1);
            const int nidx = t >> 6;
            const uint32_t buf = sbase + SM_BUF + b * STAGE_BYTES;
            const uint32_t fullb = sbase + SM_FULL + 8 * b;
            const int x = k * TKE;
            const int ay = pm * 256 + (int)rank * 128;
            const int by = nidx * 256 + (int)rank * 128;
            if (rank == 0) MBAR_EXPECT_TX(fullb, STAGE_TX);
            tma2d_cg2(buf,              &tmAh, x, ay, fullb);
            tma2d_cg2(buf + AB_QTR,     &tmAl, x, ay, fullb);
            tma2d_cg2(buf + 2 * AB_QTR, &tmBh, x, by, fullb);
            tma2d_cg2(buf + 3 * AB_QTR, &tmBl, x, by, fullb);
        }
    }

    if (tid == 192 && rank == 0) {   // MMA issuer, leader
        int pf[NBUF] = {0, 0, 0}, pbank[2] = {0, 0};
        int ti = 0, k = 0;
        for (int s = 0; s < total; s++) {
            const int b = s % NBUF;
            if (k == 0 && ti >= 2) {
                const int bk = ti & 1;
                mbar_wait(sbase + SM_BANKF + 8 * bk, pbank[bk]);
                pbank[bk] ^= 1;
            }
            mbar_wait(sbase + SM_FULL + 8 * b, pf[b]);
            pf[b] ^= 1;

            const uint32_t dst = tmem + (uint32_t)((ti & 1) * 256);
            const uint32_t bufb = sbase + SM_BUF + b * STAGE_BYTES;
            uint64_t adh = mk_desc(bufb);
            uint64_t adl = mk_desc(bufb + AB_QTR);
            uint64_t bdh = mk_desc(bufb + 2 * AB_QTR);
            uint64_t bdl = mk_desc(bufb + 3 * AB_QTR);
#pragma unroll
            for (int ks = 0; ks < 4; ks++) {
                mma_bf16_ss_cg2(dst, adh + 2 * ks, bdh + 2 * ks, IDESC2,
                                (k == 0 && ks == 0) ? 0u : 1u);
                mma_bf16_ss_cg2(dst, adh + 2 * ks, bdl + 2 * ks, IDESC2, 1u);
                mma_bf16_ss_cg2(dst, adl + 2 * ks, bdh + 2 * ks, IDESC2, 1u);
            }
            TC_COMMIT_MC2(sbase + SM_DONE + 8 * b, 3);
            if (k == KSTG - 1)
                TC_COMMIT_MC2(sbase + SM_TILED + 8 * (ti & 1), 3);

            if (++k == KSTG) { k = 0; ti++; }
        }
    }

    if (wid < 4) {   // epilogue, both CTAs
        int ptile[2] = {0, 0};
        for (int i = 0; i < myN; i++) {
            const int t = p + i * NPAIR;
            const int pm = t & (MT - 1);
            const int nidx = t >> 6;
            float* C;
            const float* bvec;
            int lcol;
            if (fused) {
                const int mtx = nidx / 5;
                C = (mtx == 0) ? cq : (mtx == 1) ? ck : cv;
                bvec = (mtx == 0) ? b0 : (mtx == 1) ? b1 : b2;
                lcol = (nidx % 5) * TN;
            } else {
                C = cq;
                bvec = b0;
                lcol = nidx * TN;
            }
            const int bk = i & 1;
            mbar_wait(sbase + SM_TILED + 8 * bk, ptile[bk]);
            ptile[bk] ^= 1;
            TC_FENCE_AFTER();

            const uint32_t tb = tmem + (uint32_t)(bk * 256);
            float* crow = C + (size_t)(pm * 256 + (int)rank * 128 + wid * 32 + lane) * DIM + lcol;
#pragma unroll
            for (int cc = 0; cc < 8; cc++) {
                uint32_t r[32];
                LDTM_X32(r, tb + cc * 32);
                TC_WAIT_LD();
                float4* cp = (float4*)(crow + cc * 32);
#pragma unroll
                for (int q = 0; q < 8; q++) {
                    float4 bb = *(const float4*)(bvec + lcol + cc * 32 + q * 4);
                    float4 v;
                    v.x = __uint_as_float(r[4 * q + 0]) + bb.x;
                    v.y = __uint_as_float(r[4 * q + 1]) + bb.y;
                    v.z = __uint_as_float(r[4 * q + 2]) + bb.z;
                    v.w = __uint_as_float(r[4 * q + 3]) + bb.w;
                    cp[q] = v;
                }
            }
            TC_FENCE_BEFORE();
            asm volatile("bar.sync 1, 128;" ::: "memory");
            if (tid == 0)
                MBAR_ARRIVE_LEADER(sbase + SM_BANKF + 8 * bk);
        }
    }

    __syncthreads();
    if (wid == 0) TC_DEALLOC2(tmem, 512);
    CLUSTER_SYNC();

#else  // ------- wmma fallback (family/generic; correctness net) -------------
    using namespace nvcuda;
    const int GLDS = 40;
    __nv_bfloat16* sAh = (__nv_bfloat16*)smc;
    __nv_bfloat16* sAl = sAh + 128 * GLDS;
    __nv_bfloat16* sBh = sAl + 128 * GLDS;
    __nv_bfloat16* sBl = sBh + 128 * GLDS;

    const int wm = (wid & 1) * 64;
    const int wn = (wid >> 1) * 32;
    const int r0 = tid >> 2;
    const int c0 = (tid & 3) * 8;
    const int p = blockIdx.x >> 1;
    const int rk = blockIdx.x & 1;
    const int myN = (ntiles > p) ? ((ntiles - 1 - p) / NPAIR + 1) : 0;

    for (int it = 0; it < myN; it++) {
        const int t = p + it * NPAIR;
        const int pm = t & (MT - 1);
        const int nidx = t >> 6;
        float* C;
        const float* bvec;
        int lcol;
        if (fused) {
            const int mtx = nidx / 5;
            C = (mtx == 0) ? cq : (mtx == 1) ? ck : cv;
            bvec = (mtx == 0) ? b0 : (mtx == 1) ? b1 : b2;
            lcol = (nidx % 5) * TN;
        } else { C = cq; bvec = b0; lcol = nidx * TN; }
        const int bm = pm * 256 + rk * 128;
        const int bng = nidx * TN;

        for (int half = 0; half < 2; half++) {
            const int bnh = bng + half * 128;
            wmma::fragment<wmma::accumulator, 16, 16, 16, float> acc[4][2];
#pragma unroll
            for (int i = 0; i < 4; i++)
#pragma unroll
                for (int j = 0; j < 2; j++) wmma::fill_fragment(acc[i][j], 0.0f);

            for (int k0 = 0; k0 < DIM; k0 += 32) {
                __syncthreads();
#pragma unroll
                for (int rr = 0; rr < 2; rr++) {
                    int row = r0 + rr * 64;
                    size_t ga = (size_t)(bm + row) * DIM + k0 + c0;
                    size_t gb = (size_t)(bnh + row) * DIM + k0 + c0;
                    *(uint4*)&sAh[row * GLDS + c0] = *(const uint4*)(Ah + ga);
                    *(uint4*)&sAl[row * GLDS + c0] = *(const uint4*)(Al + ga);
                    *(uint4*)&sBh[row * GLDS + c0] = *(const uint4*)(Bh + gb);
                    *(uint4*)&sBl[row * GLDS + c0] = *(const uint4*)(Bl + gb);
                }
                __syncthreads();
#pragma unroll
                for (int kk = 0; kk < 32; kk += 16) {
                    wmma::fragment<wmma::matrix_a, 16, 16, 16, __nv_bfloat16, wmma::row_major> fah[4], fal[4];
                    wmma::fragment<wmma::matrix_b, 16, 16, 16, __nv_bfloat16, wmma::col_major> fbh[2], fbl[2];
#pragma unroll
                    for (int i = 0; i < 4; i++) {
                        wmma::load_matrix_sync(fah[i], &sAh[(wm + i * 16) * GLDS + kk], GLDS);
                        wmma::load_matrix_sync(fal[i], &sAl[(wm + i * 16) * GLDS + kk], GLDS);
                    }
#pragma unroll
                    for (int j = 0; j < 2; j++) {
                        wmma::load_matrix_sync(fbh[j], &sBh[(wn + j * 16) * GLDS + kk], GLDS);
                        wmma::load_matrix_sync(fbl[j], &sBl[(wn + j * 16) * GLDS + kk], GLDS);
                    }
#pragma unroll
                    for (int i = 0; i < 4; i++)
#pragma unroll
                        for (int j = 0; j < 2; j++) {
                            wmma::mma_sync(acc[i][j], fah[i], fbh[j], acc[i][j]);
                            wmma::mma_sync(acc[i][j], fah[i], fbl[j], acc[i][j]);
                            wmma::mma_sync(acc[i][j], fal[i], fbh[j], acc[i][j]);
                        }
                }
            }
#pragma unroll
            for (int i = 0; i < 4; i++)
#pragma unroll
                for (int j = 0; j < 2; j++)
                    wmma::store_matrix_sync(&C[(size_t)(bm + wm + i * 16) * DIM + lcol + half * 128 + wn + j * 16],
                                            acc[i][j], DIM, wmma::mem_row_major);
            __syncthreads();
        }
        for (int idx = tid; idx < TM * TN; idx += 256) {
            int row = idx / TN, col = idx % TN;
            C[(size_t)(bm + row) * DIM + lcol + col] += bvec[lcol + col];
        }
        __syncthreads();
    }
#endif
}

// ---------------------------------------------------------------------------
// Windowed attention v6: both matmul phases as f32x2 packed dot products.
// qs/ks row-major (d-contig); V staged TRANSPOSED vT[c][j] (j-contig);
// P (j-contig rows, stride 68) aliases qs. Register softmax via half-warp
// shuffles. Bias pre-added by GEMM epilogue.
// ---------------------------------------------------------------------------
__global__ __launch_bounds__(256)
void attn_win(const float* __restrict__ cosp, const float* __restrict__ sinp)
{
    extern __shared__ float sm[];
    float* qs = sm;                      // [64][84]
    float* ks = qs + WIN * HDP;          // [64][84]
    float* vT = ks + WIN * HDP;          // [80][68] (col-major V)
    float* Ps = qs;                      // P [64][68] aliases qs

    const int w = blockIdx.x;
    const int h = blockIdx.y;
    const int tid = threadIdx.x;
    const size_t base = (size_t)(w * WIN) * DIM + (size_t)h * HD;

    // stage q/k with RoPE (bias already applied by GEMM)
    for (int idx = tid; idx < WIN * (HD / 2); idx += 256) {
        int row = idx / (HD / 2);
        int d   = idx % (HD / 2);
        int s   = w * WIN + row;
        float c1 = cosp[s * HD + d],          s1 = sinp[s * HD + d];
        float c2 = cosp[s * HD + d + HD / 2], s2 = sinp[s * HD + d + HD / 2];
        size_t o1 = base + (size_t)row * DIM + d;
        size_t o2 = o1 + HD / 2;

        float q1 = g_q[o1];
        float q2 = g_q[o2];
        qs[row * HDP + d]          = q1 * c1 - q2 * s1;
        qs[row * HDP + d + HD / 2] = q2 * c2 + q1 * s2;

        float k1 = g_k[o1];
        float k2 = g_k[o2];
        ks[row * HDP + d]          = k1 * c1 - k2 * s1;
        ks[row * HDP + d + HD / 2] = k2 * c2 + k1 * s2;
    }
    // stage V transposed: read v[j][c..c+3] coalesced, scatter to vT[c][j]
    for (int idx = tid; idx < WIN * (HD / 4); idx += 256) {
        int row = idx / (HD / 4);              // j
        int col = (idx % (HD / 4)) * 4;        // c base
        float4 vv = *(const float4*)(g_v + base + (size_t)row * DIM + col);
        vT[(col + 0) * VTS + row] = vv.x;
        vT[(col + 1) * VTS + row] = vv.y;
        vT[(col + 2) * VTS + row] = vv.z;
        vT[(col + 3) * VTS + row] = vv.w;
    }
    __syncthreads();

    // scores: 4x4 microtile; packed dot over d (acc2[r][c] = f32x2 pair-sum)
    const float scale = 0.11180339887498949f;
    const int ti = (tid >> 4) * 4;
    const int tj = (tid & 15) * 4;
    unsigned long long acc2[4][4];
#pragma unroll
    for (int r = 0; r < 4; r++)
#pragma unroll
        for (int c = 0; c < 4; c++) acc2[r][c] = 0ull;

    for (int d = 0; d < HD; d += 4) {
        unsigned long long q2v[4][2], k2v[4][2];
#pragma unroll
        for (int r = 0; r < 4; r++) {
            float4 qv = *(const float4*)(qs + (ti + r) * HDP + d);
            memcpy(&q2v[r][0], &qv.x, 8);
            memcpy(&q2v[r][1], &qv.z, 8);
        }
#pragma unroll
        for (int c = 0; c < 4; c++) {
            float4 kv = *(const float4*)(ks + (tj + c) * HDP + d);
            memcpy(&k2v[c][0], &kv.x, 8);
            memcpy(&k2v[c][1], &kv.z, 8);
        }
#pragma unroll
        for (int r = 0; r < 4; r++)
#pragma unroll
            for (int c = 0; c < 4; c++) {
                fma2(acc2[r][c], q2v[r][0], k2v[c][0]);
                fma2(acc2[r][c], q2v[r][1], k2v[c][1]);
            }
    }

    __syncthreads();   // qs reads complete before P overwrites

    // horizontal reduce + softmax per row (16-thread half-warp shuffles)
#pragma unroll
    for (int r = 0; r < 4; r++) {
        float s0 = hadd2(acc2[r][0]) * scale;
        float s1 = hadd2(acc2[r][1]) * scale;
        float s2 = hadd2(acc2[r][2]) * scale;
        float s3 = hadd2(acc2[r][3]) * scale;
        float m = fmaxf(fmaxf(s0, s1), fmaxf(s2, s3));
#pragma unroll
        for (int o = 8; o; o >>= 1)
            m = fmaxf(m, __shfl_xor_sync(0xffffffffu, m, o, 16));
        float e0 = __expf(s0 - m);
        float e1 = __expf(s1 - m);
        float e2 = __expf(s2 - m);
        float e3 = __expf(s3 - m);
        float s = e0 + e1 + e2 + e3;
#pragma unroll
        for (int o = 8; o; o >>= 1)
            s += __shfl_xor_sync(0xffffffffu, s, o, 16);
        float inv = 1.f / s;
        float4 pv;
        pv.x = e0 * inv; pv.y = e1 * inv; pv.z = e2 * inv; pv.w = e3 * inv;
        *(float4*)(Ps + (ti + r) * PSP + tj) = pv;
    }
    __syncthreads();

    // P@V as packed dots over j: o[r][c] = dot(P_row, vT_row)
    {
        const int pr = (tid >> 4) * 4;
        const int pc = (tid & 15) * 5;
        unsigned long long o2[4][5];
#pragma unroll
        for (int r = 0; r < 4; r++)
#pragma unroll
            for (int c = 0; c < 5; c++) o2[r][c] = 0ull;

        for (int j = 0; j < WIN; j += 4) {
            unsigned long long p2[4][2], v2[5][2];
#pragma unroll
            for (int r = 0; r < 4; r++) {
                float4 pv = *(const float4*)(Ps + (pr + r) * PSP + j);
                memcpy(&p2[r][0], &pv.x, 8);
                memcpy(&p2[r][1], &pv.z, 8);
            }
#pragma unroll
            for (int c = 0; c < 5; c++) {
                float4 vv = *(const float4*)(vT + (pc + c) * VTS + j);
                memcpy(&v2[c][0], &vv.x, 8);
                memcpy(&v2[c][1], &vv.z, 8);
            }
#pragma unroll
            for (int r = 0; r < 4; r++)
#pragma unroll
                for (int c = 0; c < 5; c++) {
                    fma2(o2[r][c], p2[r][0], v2[c][0]);
                    fma2(o2[r][c], p2[r][1], v2[c][1]);
                }
        }
#pragma unroll
        for (int r = 0; r < 4; r++) {
            size_t ob = base + (size_t)(pr + r) * DIM + pc;
#pragma unroll
            for (int c = 0; c < 5; c++) {
                float o = hadd2(o2[r][c]);
                __nv_bfloat16 hi = __float2bfloat16(o);
                g_ahi[ob + c] = hi;
                g_alo[ob + c] = __float2bfloat16(o - __bfloat162float(hi));
            }
        }
    }
}

// ---------------------------------------------------------------------------
typedef CUresult (*PFN_tmap_encode)(
    CUtensorMap*, CUtensorMapDataType, cuuint32_t, void*,
    const cuuint64_t*, const cuuint64_t*, const cuuint32_t*, const cuuint32_t*,
    CUtensorMapInterleave, CUtensorMapSwizzle, CUtensorMapL2promotion,
    CUtensorMapFloatOOBfill);

static void encode_map(PFN_tmap_encode enc, CUtensorMap* m, void* base, uint64_t rows)
{
    cuuint64_t dims[2]    = {DIM, rows};
    cuuint64_t strides[1] = {DIM * 2};
    cuuint32_t box[2]     = {64, 128};
    cuuint32_t es[2]      = {1, 1};
    enc(m, CU_TENSOR_MAP_DATA_TYPE_BFLOAT16, 2, base, dims, strides, box, es,
        CU_TENSOR_MAP_INTERLEAVE_NONE, CU_TENSOR_MAP_SWIZZLE_128B,
        CU_TENSOR_MAP_L2_PROMOTION_L2_128B, CU_TENSOR_MAP_FLOAT_OOB_FILL_NONE);
}

extern "C" void kernel_launch(void* const* d_in, const int* in_sizes, int n_in,
                              void* d_out, int out_size)
{
    const float* hs   = (const float*)d_in[0];
    const float* cosp = (const float*)d_in[1];
    const float* sinp = (const float*)d_in[2];
    const float* Wq   = (const float*)d_in[3];
    const float* bq   = (const float*)d_in[4];
    const float* Wk   = (const float*)d_in[5];
    const float* bk   = (const float*)d_in[6];
    const float* Wv   = (const float*)d_in[7];
    const float* bv   = (const float*)d_in[8];
    const float* Wp   = (const float*)d_in[9];
    const float* bp   = (const float*)d_in[10];
    float* out = (float*)d_out;

    float *pq, *pk, *pv;
    __nv_bfloat16 *pah, *pal, *pwh, *pwl;
    cudaGetSymbolAddress((void**)&pq,  g_q);
    cudaGetSymbolAddress((void**)&pk,  g_k);
    cudaGetSymbolAddress((void**)&pv,  g_v);
    cudaGetSymbolAddress((void**)&pah, g_ahi);
    cudaGetSymbolAddress((void**)&pal, g_alo);
    cudaGetSymbolAddress((void**)&pwh, g_whi);
    cudaGetSymbolAddress((void**)&pwl, g_wlo);

    PFN_tmap_encode enc = nullptr;
    cudaDriverEntryPointQueryResult qr;
    cudaGetDriverEntryPoint("cuTensorMapEncodeTiled", (void**)&enc,
                            cudaEnableDefault, &qr);
    CUtensorMap tmAh, tmAl, tmBh, tmBl;
    encode_map(enc, &tmAh, pah, SEQ);
    encode_map(enc, &tmAl, pal, SEQ);
    encode_map(enc, &tmBh, pwh, 3 * DIM);
    encode_map(enc, &tmBl, pwl, 3 * DIM);

    const int nA4 = SEQ * DIM / 4;
    const int nW4 = DIM * DIM / 4;

    cudaFuncSetAttribute(gemm_tc, cudaFuncAttributeMaxDynamicSharedMemorySize, SMEM_GEMM);
    cudaFuncSetAttribute(attn_win, cudaFuncAttributeMaxDynamicSharedMemorySize, SMEM_ATTN);

    split_kernel<<<(nA4 + 255) / 256, 256>>>(hs, pah, pal, nA4);
    split3_kernel<<<(3 * nW4 + 255) / 256, 256>>>(Wq, Wk, Wv, pwh, pwl, nW4);

    // fused QKV (biases in epilogue): 960 pair-tiles over 74 persistent pairs
    gemm_tc<<<dim3(2 * NPAIR, 1), 256, SMEM_GEMM>>>(
        tmAh, tmAl, tmBh, tmBl, pah, pal, pwh, pwl, pq, pk, pv, bq, bk, bv, 1,
        MT * (3 * DIM / TN));

    attn_win<<<dim3(NWIN, NH), 256, SMEM_ATTN>>>(cosp, sinp);

    split_kernel<<<(nW4 + 255) / 256, 256>>>(Wp, pwh, pwl, nW4);
    gemm_tc<<<dim3(2 * NPAIR, 1), 256, SMEM_GEMM>>>(
        tmAh, tmAl, tmBh, tmBl, pah, pal, pwh, pwl, out, out, out, bp, bp, bp, 0,
        MT * (DIM / TN));
}

// round 17
// speedup vs baseline: 1.2035x; 1.2035x over previous
#include <cuda_runtime.h>
#include <cuda.h>
#include <cuda_bf16.h>
#include <mma.h>
#include <cstdint>

#define SEQ   16384
#define DIM   1280
#define NH    16
#define HD    80
#define WIN   64
#define NWIN  (SEQ / WIN)
#define HDP   84
#define PSP   68   // P row stride (16B-aligned)

// tcgen05 cg2 GEMM tiling: persistent pairs, 256x256 pair tile
#define TM    128
#define TN    256
#define TKE   64
#define KSTG  (DIM / TKE)  // 20
#define NBUF  3
#define NPAIR 74
#define MT    64           // SEQ/256

// smem layout (gemm)
#define SM_TMEM   0
#define SM_FULL   8
#define SM_DONE   32
#define SM_TILED  56
#define SM_BANKF  72
#define SM_BUF    1024
#define AB_QTR    16384
#define STAGE_BYTES (4 * AB_QTR)
#define SMEM_GEMM (SM_BUF + NBUF * STAGE_BYTES)
#define STAGE_TX  (2 * STAGE_BYTES)

// attention smem: q/k/v tiles (P reuses qs; 64.5KB -> 3 CTAs/SM)
#define SMEM_ATTN (3 * WIN * HDP * (int)sizeof(float))

#if defined(__CUDA_ARCH__) && (defined(__CUDA_ARCH_FEAT_SM103_ALL) || defined(__CUDA_ARCH_FEAT_SM100_ALL))
#define TC_PATH 1
#else
#define TC_PATH 0
#endif

// ---------------------------------------------------------------------------
__device__ float g_q[SEQ * DIM];
__device__ float g_k[SEQ * DIM];
__device__ float g_v[SEQ * DIM];
__device__ __nv_bfloat16 g_ahi[SEQ * DIM];
__device__ __nv_bfloat16 g_alo[SEQ * DIM];
__device__ __nv_bfloat16 g_whi[3 * DIM * DIM];
__device__ __nv_bfloat16 g_wlo[3 * DIM * DIM];

#if TC_PATH
__device__ __forceinline__ uint32_t smem_u32(const void* p) {
    uint32_t a;
    asm("{ .reg .u64 t; cvta.to.shared.u64 t, %1; cvt.u32.u64 %0, t; }"
        : "=r"(a) : "l"(p));
    return a;
}
__device__ __forceinline__ uint32_t ctarank() {
    uint32_t r;
    asm("mov.u32 %0, %%cluster_ctarank;" : "=r"(r));
    return r;
}
#define MBAR_INIT(addr, cnt) \
    asm volatile("mbarrier.init.shared.b64 [%0], %1;" :: "r"(addr), "r"(cnt) : "memory")
#define MBAR_EXPECT_TX(addr, tx) \
    asm volatile("mbarrier.arrive.expect_tx.shared.b64 _, [%0], %1;" :: "r"(addr), "r"(tx) : "memory")
#define MBAR_ARRIVE_LEADER(addr) \
    asm volatile("{ .reg .b32 la; and.b32 la, %0, 0xFEFFFFFF; " \
                 "mbarrier.arrive.shared::cluster.b64 _, [la]; }" :: "r"(addr) : "memory")

__device__ __forceinline__ void mbar_wait(uint32_t mbar, uint32_t phase) {
    asm volatile(
        "{\n\t.reg .pred P;\n\t"
        "WL_%=:\n\t"
        "mbarrier.try_wait.parity.acquire.cta.shared::cta.b64 P, [%0], %1, 0x989680;\n\t"
        "@P bra WD_%=;\n\t"
        "bra WL_%=;\n\t"
        "WD_%=:\n\t}"
        :: "r"(mbar), "r"(phase) : "memory");
}
#define CLUSTER_SYNC() do { \
    asm volatile("barrier.cluster.arrive.aligned;" ::: "memory"); \
    asm volatile("barrier.cluster.wait.aligned;" ::: "memory"); \
} while (0)

__device__ __forceinline__ void tma2d_cg2(uint32_t saddr, const void* tmap, int x, int y,
                                          uint32_t mbar) {
    asm volatile(
        "{\n\t.reg .b32 lb;\n\tand.b32 lb, %4, 0xFEFFFFFF;\n\t"
        "cp.async.bulk.tensor.2d.cta_group::2.shared::cluster.global.tile"
        ".mbarrier::complete_tx::bytes [%0], [%1, {%2, %3}], [lb];\n\t}"
        :: "r"(saddr), "l"(tmap), "r"(x), "r"(y), "r"(mbar) : "memory");
}
__device__ __forceinline__ uint64_t mk_desc(uint32_t addr) {
    return ((uint64_t)2 << 61) | ((uint64_t)1 << 46) | ((uint64_t)64 << 32) |
           ((uint64_t)1 << 16) | (uint64_t)((addr >> 4) & 0x3FFF);
}
__device__ __forceinline__ void mma_bf16_ss_cg2(uint32_t d, uint64_t ad, uint64_t bd,
                                                uint32_t idesc, uint32_t en) {
    asm volatile(
        "{\n\t.reg .pred p;\n\tsetp.ne.u32 p, %5, 0;\n\t"
        "tcgen05.mma.cta_group::2.kind::f16 [%0], %1, %2, %3, "
        "{%4, %4, %4, %4, %4, %4, %4, %4}, p;\n\t}"
        :: "r"(d), "l"(ad), "l"(bd), "r"(idesc), "r"(0u), "r"(en) : "memory");
}
#define TC_COMMIT_MC2(mbar, mask) \
    asm volatile("tcgen05.commit.cta_group::2.mbarrier::arrive::one.shared::cluster" \
                 ".multicast::cluster.b64 [%0], %1;" :: "r"(mbar), "h"((uint16_t)(mask)) : "memory")
#define TC_ALLOC2(slot, n) \
    asm volatile("tcgen05.alloc.cta_group::2.sync.aligned.shared::cta.b32 [%0], %1;" \
                 :: "r"(slot), "r"(n) : "memory")
#define TC_RELINQ2() \
    asm volatile("tcgen05.relinquish_alloc_permit.cta_group::2.sync.aligned;")
#define TC_DEALLOC2(t, n) \
    asm volatile("tcgen05.dealloc.cta_group::2.sync.aligned.b32 %0, %1;" :: "r"(t), "r"(n))
#define TC_FENCE_AFTER()  asm volatile("tcgen05.fence::after_thread_sync;" ::: "memory")
#define TC_FENCE_BEFORE() asm volatile("tcgen05.fence::before_thread_sync;" ::: "memory")
#define TC_WAIT_LD() asm volatile("tcgen05.wait::ld.sync.aligned;" ::: "memory")

#define LDTM_X32(r, addr) \
    asm volatile("tcgen05.ld.sync.aligned.32x32b.x32.b32 " \
        "{%0,%1,%2,%3,%4,%5,%6,%7,%8,%9,%10,%11,%12,%13,%14,%15," \
        "%16,%17,%18,%19,%20,%21,%22,%23,%24,%25,%26,%27,%28,%29,%30,%31}, [%32];" \
        : "=r"((r)[0]),"=r"((r)[1]),"=r"((r)[2]),"=r"((r)[3]), \
          "=r"((r)[4]),"=r"((r)[5]),"=r"((r)[6]),"=r"((r)[7]), \
          "=r"((r)[8]),"=r"((r)[9]),"=r"((r)[10]),"=r"((r)[11]), \
          "=r"((r)[12]),"=r"((r)[13]),"=r"((r)[14]),"=r"((r)[15]), \
          "=r"((r)[16]),"=r"((r)[17]),"=r"((r)[18]),"=r"((r)[19]), \
          "=r"((r)[20]),"=r"((r)[21]),"=r"((r)[22]),"=r"((r)[23]), \
          "=r"((r)[24]),"=r"((r)[25]),"=r"((r)[26]),"=r"((r)[27]), \
          "=r"((r)[28]),"=r"((r)[29]),"=r"((r)[30]),"=r"((r)[31]) \
        : "r"(addr))

#define IDESC2 ((1u << 4) | (1u << 7) | (1u << 10) | ((TN / 8) << 17) | (16u << 24))
#endif  // TC_PATH

// ---------------------------------------------------------------------------
__global__ void split_kernel(const float* __restrict__ src,
                             __nv_bfloat16* __restrict__ hi,
                             __nv_bfloat16* __restrict__ lo, int n4)
{
    int i = blockIdx.x * blockDim.x + threadIdx.x;
    if (i >= n4) return;
    float4 v = ((const float4*)src)[i];
    __nv_bfloat16 h0 = __float2bfloat16(v.x);
    __nv_bfloat16 h1 = __float2bfloat16(v.y);
    __nv_bfloat16 h2 = __float2bfloat16(v.z);
    __nv_bfloat16 h3 = __float2bfloat16(v.w);
    __nv_bfloat16 l0 = __float2bfloat16(v.x - __bfloat162float(h0));
    __nv_bfloat16 l1 = __float2bfloat16(v.y - __bfloat162float(h1));
    __nv_bfloat16 l2 = __float2bfloat16(v.z - __bfloat162float(h2));
    __nv_bfloat16 l3 = __float2bfloat16(v.w - __bfloat162float(h3));
    __nv_bfloat162* hp = (__nv_bfloat162*)hi;
    __nv_bfloat162* lp = (__nv_bfloat162*)lo;
    hp[2 * i]     = __nv_bfloat162(h0, h1);
    hp[2 * i + 1] = __nv_bfloat162(h2, h3);
    lp[2 * i]     = __nv_bfloat162(l0, l1);
    lp[2 * i + 1] = __nv_bfloat162(l2, l3);
}

// Three weight matrices in one launch (Wq|Wk|Wv -> stacked hi/lo)
__global__ void split3_kernel(const float* __restrict__ s0,
                              const float* __restrict__ s1,
                              const float* __restrict__ s2,
                              __nv_bfloat16* __restrict__ hi,
                              __nv_bfloat16* __restrict__ lo, int n4)
{
    int gi = blockIdx.x * blockDim.x + threadIdx.x;
    int m = gi / n4;
    int i = gi - m * n4;
    if (m >= 3) return;
    const float* src = (m == 0) ? s0 : (m == 1) ? s1 : s2;
    float4 v = ((const float4*)src)[i];
    __nv_bfloat16 h0 = __float2bfloat16(v.x);
    __nv_bfloat16 h1 = __float2bfloat16(v.y);
    __nv_bfloat16 h2 = __float2bfloat16(v.z);
    __nv_bfloat16 h3 = __float2bfloat16(v.w);
    __nv_bfloat16 l0 = __float2bfloat16(v.x - __bfloat162float(h0));
    __nv_bfloat16 l1 = __float2bfloat16(v.y - __bfloat162float(h1));
    __nv_bfloat16 l2 = __float2bfloat16(v.z - __bfloat162float(h2));
    __nv_bfloat16 l3 = __float2bfloat16(v.w - __bfloat162float(h3));
    __nv_bfloat162* hp = (__nv_bfloat162*)(hi + (size_t)m * DIM * DIM);
    __nv_bfloat162* lp = (__nv_bfloat162*)(lo + (size_t)m * DIM * DIM);
    hp[2 * i]     = __nv_bfloat162(h0, h1);
    hp[2 * i + 1] = __nv_bfloat162(h2, h3);
    lp[2 * i]     = __nv_bfloat162(l0, l1);
    lp[2 * i + 1] = __nv_bfloat162(l2, l3);
}

// ---------------------------------------------------------------------------
// Persistent cg2 bf16x3 GEMM; bias added in epilogue. (Unchanged from r15.)
// ---------------------------------------------------------------------------
__global__ __launch_bounds__(256, 1) __cluster_dims__(2, 1, 1)
void gemm_tc(const __grid_constant__ CUtensorMap tmAh,
             const __grid_constant__ CUtensorMap tmAl,
             const __grid_constant__ CUtensorMap tmBh,
             const __grid_constant__ CUtensorMap tmBl,
             const __nv_bfloat16* __restrict__ Ah,
             const __nv_bfloat16* __restrict__ Al,
             const __nv_bfloat16* __restrict__ Bh,
             const __nv_bfloat16* __restrict__ Bl,
             float* cq, float* ck, float* cv,
             const float* __restrict__ b0, const float* __restrict__ b1,
             const float* __restrict__ b2, int fused, int ntiles)
{
    extern __shared__ char smc[];
    const int tid = threadIdx.x;
    const int wid = tid >> 5;

#if TC_PATH
    const int lane = tid & 31;
    const uint32_t sbase = smem_u32(smc);
    const uint32_t rank = ctarank();
    const int p = blockIdx.x >> 1;
    const int myN = (ntiles - 1 - p) / NPAIR + 1;
    const int total = myN * KSTG;

    if (tid == 0) {
#pragma unroll
        for (int s = 0; s < NBUF; s++) {
            MBAR_INIT(sbase + SM_FULL + 8 * s, 1);
            MBAR_INIT(sbase + SM_DONE + 8 * s, 1);
        }
        MBAR_INIT(sbase + SM_TILED, 1);
        MBAR_INIT(sbase + SM_TILED + 8, 1);
        MBAR_INIT(sbase + SM_BANKF, 2);
        MBAR_INIT(sbase + SM_BANKF + 8, 2);
    }
    if (wid == 0) {
        TC_ALLOC2(sbase + SM_TMEM, 512);
        TC_RELINQ2();
    }
    __syncthreads();
    CLUSTER_SYNC();

    uint32_t tmem;
    asm volatile("ld.shared.b32 %0, [%1];" : "=r"(tmem) : "r"(sbase + SM_TMEM));

    if (tid == 224) {   // TMA producer, both CTAs
        int pd[NBUF] = {0, 0, 0};
        for (int u = 0; u < total; u++) {
            const int b = u % NBUF;
            if (u >= NBUF) {
                mbar_wait(sbase + SM_DONE + 8 * b, pd[b]);
                pd[b] ^= 1;
            }
            const int ti = u / KSTG, k = u - ti * KSTG;
            const int t = p + ti * NPAIR;
            const int pm = t & (MT - 1);
            const int nidx = t >> 6;
            const uint32_t buf = sbase + SM_BUF + b * STAGE_BYTES;
            const uint32_t fullb = sbase + SM_FULL + 8 * b;
            const int x = k * TKE;
            const int ay = pm * 256 + (int)rank * 128;
            const int by = nidx * 256 + (int)rank * 128;
            if (rank == 0) MBAR_EXPECT_TX(fullb, STAGE_TX);
            tma2d_cg2(buf,              &tmAh, x, ay, fullb);
            tma2d_cg2(buf + AB_QTR,     &tmAl, x, ay, fullb);
            tma2d_cg2(buf + 2 * AB_QTR, &tmBh, x, by, fullb);
            tma2d_cg2(buf + 3 * AB_QTR, &tmBl, x, by, fullb);
        }
    }

    if (tid == 192 && rank == 0) {   // MMA issuer, leader
        int pf[NBUF] = {0, 0, 0}, pbank[2] = {0, 0};
        int ti = 0, k = 0;
        for (int s = 0; s < total; s++) {
            const int b = s % NBUF;
            if (k == 0 && ti >= 2) {
                const int bk = ti & 1;
                mbar_wait(sbase + SM_BANKF + 8 * bk, pbank[bk]);
                pbank[bk] ^= 1;
            }
            mbar_wait(sbase + SM_FULL + 8 * b, pf[b]);
            pf[b] ^= 1;

            const uint32_t dst = tmem + (uint32_t)((ti & 1) * 256);
            const uint32_t bufb = sbase + SM_BUF + b * STAGE_BYTES;
            uint64_t adh = mk_desc(bufb);
            uint64_t adl = mk_desc(bufb + AB_QTR);
            uint64_t bdh = mk_desc(bufb + 2 * AB_QTR);
            uint64_t bdl = mk_desc(bufb + 3 * AB_QTR);
#pragma unroll
            for (int ks = 0; ks < 4; ks++) {
                mma_bf16_ss_cg2(dst, adh + 2 * ks, bdh + 2 * ks, IDESC2,
                                (k == 0 && ks == 0) ? 0u : 1u);
                mma_bf16_ss_cg2(dst, adh + 2 * ks, bdl + 2 * ks, IDESC2, 1u);
                mma_bf16_ss_cg2(dst, adl + 2 * ks, bdh + 2 * ks, IDESC2, 1u);
            }
            TC_COMMIT_MC2(sbase + SM_DONE + 8 * b, 3);
            if (k == KSTG - 1)
                TC_COMMIT_MC2(sbase + SM_TILED + 8 * (ti & 1), 3);

            if (++k == KSTG) { k = 0; ti++; }
        }
    }

    if (wid < 4) {   // epilogue, both CTAs
        int ptile[2] = {0, 0};
        for (int i = 0; i < myN; i++) {
            const int t = p + i * NPAIR;
            const int pm = t & (MT - 1);
            const int nidx = t >> 6;
            float* C;
            const float* bvec;
            int lcol;
            if (fused) {
                const int mtx = nidx / 5;
                C = (mtx == 0) ? cq : (mtx == 1) ? ck : cv;
                bvec = (mtx == 0) ? b0 : (mtx == 1) ? b1 : b2;
                lcol = (nidx % 5) * TN;
            } else {
                C = cq;
                bvec = b0;
                lcol = nidx * TN;
            }
            const int bk = i & 1;
            mbar_wait(sbase + SM_TILED + 8 * bk, ptile[bk]);
            ptile[bk] ^= 1;
            TC_FENCE_AFTER();

            const uint32_t tb = tmem + (uint32_t)(bk * 256);
            float* crow = C + (size_t)(pm * 256 + (int)rank * 128 + wid * 32 + lane) * DIM + lcol;
#pragma unroll
            for (int cc = 0; cc < 8; cc++) {
                uint32_t r[32];
                LDTM_X32(r, tb + cc * 32);
                TC_WAIT_LD();
                float4* cp = (float4*)(crow + cc * 32);
#pragma unroll
                for (int q = 0; q < 8; q++) {
                    float4 bb = *(const float4*)(bvec + lcol + cc * 32 + q * 4);
                    float4 v;
                    v.x = __uint_as_float(r[4 * q + 0]) + bb.x;
                    v.y = __uint_as_float(r[4 * q + 1]) + bb.y;
                    v.z = __uint_as_float(r[4 * q + 2]) + bb.z;
                    v.w = __uint_as_float(r[4 * q + 3]) + bb.w;
                    cp[q] = v;
                }
            }
            TC_FENCE_BEFORE();
            asm volatile("bar.sync 1, 128;" ::: "memory");
            if (tid == 0)
                MBAR_ARRIVE_LEADER(sbase + SM_BANKF + 8 * bk);
        }
    }

    __syncthreads();
    if (wid == 0) TC_DEALLOC2(tmem, 512);
    CLUSTER_SYNC();

#else  // ------- wmma fallback (family/generic; correctness net) -------------
    using namespace nvcuda;
    const int GLDS = 40;
    __nv_bfloat16* sAh = (__nv_bfloat16*)smc;
    __nv_bfloat16* sAl = sAh + 128 * GLDS;
    __nv_bfloat16* sBh = sAl + 128 * GLDS;
    __nv_bfloat16* sBl = sBh + 128 * GLDS;

    const int wm = (wid & 1) * 64;
    const int wn = (wid >> 1) * 32;
    const int r0 = tid >> 2;
    const int c0 = (tid & 3) * 8;
    const int p = blockIdx.x >> 1;
    const int rk = blockIdx.x & 1;
    const int myN = (ntiles > p) ? ((ntiles - 1 - p) / NPAIR + 1) : 0;

    for (int it = 0; it < myN; it++) {
        const int t = p + it * NPAIR;
        const int pm = t & (MT - 1);
        const int nidx = t >> 6;
        float* C;
        const float* bvec;
        int lcol;
        if (fused) {
            const int mtx = nidx / 5;
            C = (mtx == 0) ? cq : (mtx == 1) ? ck : cv;
            bvec = (mtx == 0) ? b0 : (mtx == 1) ? b1 : b2;
            lcol = (nidx % 5) * TN;
        } else { C = cq; bvec = b0; lcol = nidx * TN; }
        const int bm = pm * 256 + rk * 128;
        const int bng = nidx * TN;

        for (int half = 0; half < 2; half++) {
            const int bnh = bng + half * 128;
            wmma::fragment<wmma::accumulator, 16, 16, 16, float> acc[4][2];
#pragma unroll
            for (int i = 0; i < 4; i++)
#pragma unroll
                for (int j = 0; j < 2; j++) wmma::fill_fragment(acc[i][j], 0.0f);

            for (int k0 = 0; k0 < DIM; k0 += 32) {
                __syncthreads();
#pragma unroll
                for (int rr = 0; rr < 2; rr++) {
                    int row = r0 + rr * 64;
                    size_t ga = (size_t)(bm + row) * DIM + k0 + c0;
                    size_t gb = (size_t)(bnh + row) * DIM + k0 + c0;
                    *(uint4*)&sAh[row * GLDS + c0] = *(const uint4*)(Ah + ga);
                    *(uint4*)&sAl[row * GLDS + c0] = *(const uint4*)(Al + ga);
                    *(uint4*)&sBh[row * GLDS + c0] = *(const uint4*)(Bh + gb);
                    *(uint4*)&sBl[row * GLDS + c0] = *(const uint4*)(Bl + gb);
                }
                __syncthreads();
#pragma unroll
                for (int kk = 0; kk < 32; kk += 16) {
                    wmma::fragment<wmma::matrix_a, 16, 16, 16, __nv_bfloat16, wmma::row_major> fah[4], fal[4];
                    wmma::fragment<wmma::matrix_b, 16, 16, 16, __nv_bfloat16, wmma::col_major> fbh[2], fbl[2];
#pragma unroll
                    for (int i = 0; i < 4; i++) {
                        wmma::load_matrix_sync(fah[i], &sAh[(wm + i * 16) * GLDS + kk], GLDS);
                        wmma::load_matrix_sync(fal[i], &sAl[(wm + i * 16) * GLDS + kk], GLDS);
                    }
#pragma unroll
                    for (int j = 0; j < 2; j++) {
                        wmma::load_matrix_sync(fbh[j], &sBh[(wn + j * 16) * GLDS + kk], GLDS);
                        wmma::load_matrix_sync(fbl[j], &sBl[(wn + j * 16) * GLDS + kk], GLDS);
                    }
#pragma unroll
                    for (int i = 0; i < 4; i++)
#pragma unroll
                        for (int j = 0; j < 2; j++) {
                            wmma::mma_sync(acc[i][j], fah[i], fbh[j], acc[i][j]);
                            wmma::mma_sync(acc[i][j], fah[i], fbl[j], acc[i][j]);
                            wmma::mma_sync(acc[i][j], fal[i], fbh[j], acc[i][j]);
                        }
                }
            }
#pragma unroll
            for (int i = 0; i < 4; i++)
#pragma unroll
                for (int j = 0; j < 2; j++)
                    wmma::store_matrix_sync(&C[(size_t)(bm + wm + i * 16) * DIM + lcol + half * 128 + wn + j * 16],
                                            acc[i][j], DIM, wmma::mem_row_major);
            __syncthreads();
        }
        for (int idx = tid; idx < TM * TN; idx += 256) {
            int row = idx / TN, col = idx % TN;
            C[(size_t)(bm + row) * DIM + lcol + col] += bvec[lcol + col];
        }
        __syncthreads();
    }
#endif
}

// ---------------------------------------------------------------------------
// Windowed attention v7 (= r15 + conflict-free score columns): lane c=tid&15
// handles score cols {c, c+16, c+32, c+48} -> K-row LDS lane stride 84 floats
// (20 mod 32, conflict-free phases) instead of 336 (16 mod 32, 4-way).
// Scores in registers; half-warp shuffle softmax; P (stride 68) aliases qs;
// vectorized float4 P reads in PV. Bias pre-added by GEMM epilogue.
// ---------------------------------------------------------------------------
__global__ __launch_bounds__(256)
void attn_win(const float* __restrict__ cosp, const float* __restrict__ sinp)
{
    extern __shared__ float sm[];
    float* qs = sm;                    // [64][84]; P [64][68] aliases it later
    float* ks = qs + WIN * HDP;        // [64][84]
    float* vs = ks + WIN * HDP;        // [64][84]
    float* Ps = qs;

    const int w = blockIdx.x;
    const int h = blockIdx.y;
    const int tid = threadIdx.x;
    const size_t base = (size_t)(w * WIN) * DIM + (size_t)h * HD;

    for (int idx = tid; idx < WIN * (HD / 2); idx += 256) {
        int row = idx / (HD / 2);
        int d   = idx % (HD / 2);
        int s   = w * WIN + row;
        float c1 = cosp[s * HD + d],          s1 = sinp[s * HD + d];
        float c2 = cosp[s * HD + d + HD / 2], s2 = sinp[s * HD + d + HD / 2];
        size_t o1 = base + (size_t)row * DIM + d;
        size_t o2 = o1 + HD / 2;

        float q1 = g_q[o1];
        float q2 = g_q[o2];
        qs[row * HDP + d]          = q1 * c1 - q2 * s1;
        qs[row * HDP + d + HD / 2] = q2 * c2 + q1 * s2;

        float k1 = g_k[o1];
        float k2 = g_k[o2];
        ks[row * HDP + d]          = k1 * c1 - k2 * s1;
        ks[row * HDP + d + HD / 2] = k2 * c2 + k1 * s2;
    }
    for (int idx = tid; idx < WIN * (HD / 4); idx += 256) {
        int row = idx / (HD / 4);
        int col = (idx % (HD / 4)) * 4;
        size_t g = base + (size_t)row * DIM + col;
        *(float4*)(vs + row * HDP + col) = *(const float4*)(g_v + g);
    }
    __syncthreads();

    // scores: 4 rows x cols {cj,cj+16,cj+32,cj+48}; conflict-free K loads
    const float scale = 0.11180339887498949f;
    const int ti = (tid >> 4) * 4;
    const int cj = tid & 15;
    float acc[4][4];
#pragma unroll
    for (int r = 0; r < 4; r++)
#pragma unroll
        for (int c = 0; c < 4; c++) acc[r][c] = 0.f;

    for (int d = 0; d < HD; d += 4) {
        float4 qv[4], kv[4];
#pragma unroll
        for (int r = 0; r < 4; r++) qv[r] = *(const float4*)(qs + (ti + r) * HDP + d);
#pragma unroll
        for (int c = 0; c < 4; c++) kv[c] = *(const float4*)(ks + (cj + 16 * c) * HDP + d);
#pragma unroll
        for (int r = 0; r < 4; r++)
#pragma unroll
            for (int c = 0; c < 4; c++)
                acc[r][c] += qv[r].x * kv[c].x + qv[r].y * kv[c].y
                           + qv[r].z * kv[c].z + qv[r].w * kv[c].w;
    }

    __syncthreads();   // qs reads complete before P overwrites

    // softmax per row across the 16-thread half-warp; scatter P (stride-1
    // across lanes per column group -> conflict-free stores)
#pragma unroll
    for (int r = 0; r < 4; r++) {
        float m = fmaxf(fmaxf(acc[r][0] * scale, acc[r][1] * scale),
                        fmaxf(acc[r][2] * scale, acc[r][3] * scale));
#pragma unroll
        for (int o = 8; o; o >>= 1)
            m = fmaxf(m, __shfl_xor_sync(0xffffffffu, m, o, 16));
        float e0 = __expf(acc[r][0] * scale - m);
        float e1 = __expf(acc[r][1] * scale - m);
        float e2 = __expf(acc[r][2] * scale - m);
        float e3 = __expf(acc[r][3] * scale - m);
        float s = e0 + e1 + e2 + e3;
#pragma unroll
        for (int o = 8; o; o >>= 1)
            s += __shfl_xor_sync(0xffffffffu, s, o, 16);
        float inv = 1.f / s;
        float* pr = Ps + (ti + r) * PSP + cj;
        pr[0]  = e0 * inv;
        pr[16] = e1 * inv;
        pr[32] = e2 * inv;
        pr[48] = e3 * inv;
    }
    __syncthreads();

    // P@V: vectorized float4 P reads over j-groups of 4; V from smem
    {
        const int pr = (tid >> 4) * 4;
        const int pc = (tid & 15) * 5;
        float o[4][5];
#pragma unroll
        for (int r = 0; r < 4; r++)
#pragma unroll
            for (int c = 0; c < 5; c++) o[r][c] = 0.f;

        for (int j = 0; j < WIN; j += 4) {
            float4 p4[4];
#pragma unroll
            for (int r = 0; r < 4; r++)
                p4[r] = *(const float4*)(Ps + (pr + r) * PSP + j);
#pragma unroll
            for (int jj = 0; jj < 4; jj++) {
                float vv[5];
                const float* vj = vs + (j + jj) * HDP + pc;
#pragma unroll
                for (int c = 0; c < 5; c++) vv[c] = vj[c];
                float pj[4] = { ((const float*)&p4[0])[jj], ((const float*)&p4[1])[jj],
                                ((const float*)&p4[2])[jj], ((const float*)&p4[3])[jj] };
#pragma unroll
                for (int r = 0; r < 4; r++)
#pragma unroll
                    for (int c = 0; c < 5; c++) o[r][c] += pj[r] * vv[c];
            }
        }
#pragma unroll
        for (int r = 0; r < 4; r++) {
            size_t ob = base + (size_t)(pr + r) * DIM + pc;
#pragma unroll
            for (int c = 0; c < 5; c++) {
                __nv_bfloat16 hi = __float2bfloat16(o[r][c]);
                g_ahi[ob + c] = hi;
                g_alo[ob + c] = __float2bfloat16(o[r][c] - __bfloat162float(hi));
            }
        }
    }
}

// ---------------------------------------------------------------------------
typedef CUresult (*PFN_tmap_encode)(
    CUtensorMap*, CUtensorMapDataType, cuuint32_t, void*,
    const cuuint64_t*, const cuuint64_t*, const cuuint32_t*, const cuuint32_t*,
    CUtensorMapInterleave, CUtensorMapSwizzle, CUtensorMapL2promotion,
    CUtensorMapFloatOOBfill);

static void encode_map(PFN_tmap_encode enc, CUtensorMap* m, void* base, uint64_t rows)
{
    cuuint64_t dims[2]    = {DIM, rows};
    cuuint64_t strides[1] = {DIM * 2};
    cuuint32_t box[2]     = {64, 128};
    cuuint32_t es[2]      = {1, 1};
    enc(m, CU_TENSOR_MAP_DATA_TYPE_BFLOAT16, 2, base, dims, strides, box, es,
        CU_TENSOR_MAP_INTERLEAVE_NONE, CU_TENSOR_MAP_SWIZZLE_128B,
        CU_TENSOR_MAP_L2_PROMOTION_L2_128B, CU_TENSOR_MAP_FLOAT_OOB_FILL_NONE);
}

extern "C" void kernel_launch(void* const* d_in, const int* in_sizes, int n_in,
                              void* d_out, int out_size)
{
    const float* hs   = (const float*)d_in[0];
    const float* cosp = (const float*)d_in[1];
    const float* sinp = (const float*)d_in[2];
    const float* Wq   = (const float*)d_in[3];
    const float* bq   = (const float*)d_in[4];
    const float* Wk   = (const float*)d_in[5];
    const float* bk   = (const float*)d_in[6];
    const float* Wv   = (const float*)d_in[7];
    const float* bv   = (const float*)d_in[8];
    const float* Wp   = (const float*)d_in[9];
    const float* bp   = (const float*)d_in[10];
    float* out = (float*)d_out;

    float *pq, *pk, *pv;
    __nv_bfloat16 *pah, *pal, *pwh, *pwl;
    cudaGetSymbolAddress((void**)&pq,  g_q);
    cudaGetSymbolAddress((void**)&pk,  g_k);
    cudaGetSymbolAddress((void**)&pv,  g_v);
    cudaGetSymbolAddress((void**)&pah, g_ahi);
    cudaGetSymbolAddress((void**)&pal, g_alo);
    cudaGetSymbolAddress((void**)&pwh, g_whi);
    cudaGetSymbolAddress((void**)&pwl, g_wlo);

    PFN_tmap_encode enc = nullptr;
    cudaDriverEntryPointQueryResult qr;
    cudaGetDriverEntryPoint("cuTensorMapEncodeTiled", (void**)&enc,
                            cudaEnableDefault, &qr);
    CUtensorMap tmAh, tmAl, tmBh, tmBl;
    encode_map(enc, &tmAh, pah, SEQ);
    encode_map(enc, &tmAl, pal, SEQ);
    encode_map(enc, &tmBh, pwh, 3 * DIM);
    encode_map(enc, &tmBl, pwl, 3 * DIM);

    const int nA4 = SEQ * DIM / 4;
    const int nW4 = DIM * DIM / 4;

    cudaFuncSetAttribute(gemm_tc, cudaFuncAttributeMaxDynamicSharedMemorySize, SMEM_GEMM);
    cudaFuncSetAttribute(attn_win, cudaFuncAttributeMaxDynamicSharedMemorySize, SMEM_ATTN);

    split_kernel<<<(nA4 + 255) / 256, 256>>>(hs, pah, pal, nA4);
    split3_kernel<<<(3 * nW4 + 255) / 256, 256>>>(Wq, Wk, Wv, pwh, pwl, nW4);

    // fused QKV (biases in epilogue): 960 pair-tiles over 74 persistent pairs
    gemm_tc<<<dim3(2 * NPAIR, 1), 256, SMEM_GEMM>>>(
        tmAh, tmAl, tmBh, tmBl, pah, pal, pwh, pwl, pq, pk, pv, bq, bk, bv, 1,
        MT * (3 * DIM / TN));

    attn_win<<<dim3(NWIN, NH), 256, SMEM_ATTN>>>(cosp, sinp);

    split_kernel<<<(nW4 + 255) / 256, 256>>>(Wp, pwh, pwl, nW4);
    gemm_tc<<<dim3(2 * NPAIR, 1), 256, SMEM_GEMM>>>(
        tmAh, tmAl, tmBh, tmBl, pah, pal, pwh, pwl, out, out, out, bp, bp, bp, 0,
        MT * (DIM / TN));
}